// round 12
// baseline (speedup 1.0000x reference)
#include <cuda_runtime.h>
#include <cstdint>

// ---------------------------------------------------------------------------
// Scratch (allocation-free __device__ globals), padded layouts: HP=H+2, WP=W+4
//   (left pad 1, right pad 3 -> every row 16B aligned; borders hold zeros)
// ---------------------------------------------------------------------------
__device__ __align__(16) float g_bufA[2 * 64 * 1026 * 1028];
__device__ __align__(16) float g_bufB[2 * 64 * 1026 * 1028];
__device__ __align__(16) float g_h[2 * 1026 * 1028];       // shuffled image, padded
__device__ __align__(16) float g_xpad[2 * 258 * 260];      // padded network input
__device__ __align__(16) unsigned long long g_wpack[46296];  // packed weight pairs

// ---------------------------------------------------------------------------
// f32x2 + cp.async helpers
// ---------------------------------------------------------------------------
__device__ __forceinline__ void ffma2(uint64_t& d, uint64_t a, uint64_t b) {
    asm("fma.rn.f32x2 %0, %1, %2, %0;" : "+l"(d) : "l"(a), "l"(b));
}
__device__ __forceinline__ uint64_t dup2f(float v) {
    uint64_t r; asm("mov.b64 %0, {%1, %1};" : "=l"(r) : "f"(v)); return r;
}
__device__ __forceinline__ float lo_f(uint64_t v) { return __uint_as_float((uint32_t)v); }
__device__ __forceinline__ float hi_f(uint64_t v) { return __uint_as_float((uint32_t)(v >> 32)); }

__device__ __forceinline__ uint32_t s2u(const void* p) {
    return (uint32_t)__cvta_generic_to_shared(p);
}
__device__ __forceinline__ void cp16(uint32_t d, const void* s) {
    asm volatile("cp.async.cg.shared.global [%0], [%1], 16;" :: "r"(d), "l"(s));
}
__device__ __forceinline__ void cp8(uint32_t d, const void* s) {
    asm volatile("cp.async.ca.shared.global [%0], [%1], 8;" :: "r"(d), "l"(s));
}
__device__ __forceinline__ void cp_commit() { asm volatile("cp.async.commit_group;"); }
__device__ __forceinline__ void cp_wait0()  { asm volatile("cp.async.wait_group 0;" ::: "memory"); }

#define CONV_NT(COUT) ((((((COUT) > 32 ? 32 : (COUT)) + 7) & ~7) / 8) * 32)

// ---------------------------------------------------------------------------
// conv3x3 + ReLU on padded tensors, cp.async staging, FFMA2 compute.
//   Pixel tile 32x8; thread: 8 px x 8 co (4 packed co-pairs) = 32 f32x2 accs.
//   Input smem: plain floats, row stride 36 (conflict-free LDS.128 phases).
//   Weights: pre-packed (co,co+1) u64 pairs, verbatim 16B cp.async.
// ---------------------------------------------------------------------------
template <int CIN, int COUT>
__global__ void __launch_bounds__(CONV_NT(COUT), 640 / CONV_NT(COUT))
conv3x3_cp(const float* __restrict__ in,
           const unsigned long long* __restrict__ wpack,
           float* __restrict__ out, int H, int W) {
    constexpr int CO_TILE  = (COUT > 32) ? 32 : COUT;
    constexpr int CO_PAD   = (CO_TILE + 7) & ~7;
    constexpr int CO_TILES = (COUT + CO_TILE - 1) / CO_TILE;
    constexpr int NT       = (CO_PAD / 8) * 32;
    constexpr int CC       = (CIN >= 4) ? 4 : CIN;
    constexpr int NCHUNK   = CIN / CC;
    constexpr int WSLICE   = (CO_PAD / 2) * CC * 9;   // u64 per chunk
    constexpr int W16      = WSLICE / 2;              // 16B cp ops per chunk
    constexpr int IN_OPS   = CC * 10 * 9;             // 8x16B + 1x8B per row

    __shared__ __align__(16) float s_in[2][CC][10][36];
    __shared__ __align__(16) unsigned long long s_w[2][CO_PAD / 2][CC][9];

    const int tid  = threadIdx.x;
    const int n    = blockIdx.z / CO_TILES;
    const int tile = blockIdx.z % CO_TILES;
    const int gx0  = blockIdx.x * 32;
    const int gy0  = blockIdx.y * 8;
    const int HP = H + 2, WP = W + 4;

    const int cog = tid >> 5;
    const int pix = tid & 31;
    const int row = pix >> 2;
    const int x0  = (pix & 3) * 8;

    uint64_t acc[4][8];
#pragma unroll
    for (int g = 0; g < 4; ++g)
#pragma unroll
        for (int p = 0; p < 8; ++p) acc[g][p] = 0ull;

    const uint32_t si0 = s2u(&s_in[0][0][0][0]);
    const uint32_t sw0 = s2u(&s_w[0][0][0][0]);

    auto stage = [&](int ch) {
        const int buf = ch & 1;
        const int c0  = ch * CC;
        for (int i = tid; i < IN_OPS; i += NT) {
            int seg = i % 9, rr = i / 9;
            int c = rr / 10, r = rr % 10;
            const float* src = in + ((size_t)(n * CIN + c0 + c) * HP + (gy0 + r)) * WP
                                  + gx0 + seg * 4;
            uint32_t dst = si0 + (uint32_t)((buf * CC + c) * 10 + r) * 144u + seg * 16u;
            if (seg < 8) cp16(dst, src); else cp8(dst, src);
        }
        const char* wsrc = (const char*)(wpack + (size_t)(tile * NCHUNK + ch) * WSLICE);
        uint32_t wdst = sw0 + buf * (WSLICE * 8);
        for (int i = tid; i < W16; i += NT) cp16(wdst + i * 16u, wsrc + i * 16);
    };

    auto compute = [&](int buf) {
#pragma unroll 2
        for (int c = 0; c < CC; ++c) {
#pragma unroll
            for (int ky = 0; ky < 3; ++ky) {
                const float* rp = &s_in[buf][c][row + ky][x0];
                float4 A4 = *(const float4*)rp;
                float4 B4 = *(const float4*)(rp + 4);
                float4 C4 = *(const float4*)(rp + 8);
                float f[12] = {A4.x, A4.y, A4.z, A4.w, B4.x, B4.y, B4.z, B4.w,
                               C4.x, C4.y, C4.z, C4.w};
                uint64_t D[10];
#pragma unroll
                for (int i = 0; i < 10; ++i) D[i] = dup2f(f[i]);
#pragma unroll
                for (int g = 0; g < 4; ++g) {
                    const uint64_t w0 = s_w[buf][cog * 4 + g][c][ky * 3 + 0];
                    const uint64_t w1 = s_w[buf][cog * 4 + g][c][ky * 3 + 1];
                    const uint64_t w2 = s_w[buf][cog * 4 + g][c][ky * 3 + 2];
#pragma unroll
                    for (int p = 0; p < 8; ++p) {
                        ffma2(acc[g][p], D[p],     w0);
                        ffma2(acc[g][p], D[p + 1], w1);
                        ffma2(acc[g][p], D[p + 2], w2);
                    }
                }
            }
        }
    };

    stage(0); cp_commit();
    for (int ch = 0; ch < NCHUNK; ++ch) {
        cp_wait0();
        __syncthreads();                 // all data visible; all warps done with prev buf
        if (ch + 1 < NCHUNK) { stage(ch + 1); cp_commit(); }
        compute(ch & 1);
    }

    // epilogue: ReLU + scalar stores into padded layout (col offset +1 -> unaligned)
    const int gy = gy0 + row;
#pragma unroll
    for (int g = 0; g < 4; ++g) {
        const int co0 = tile * CO_TILE + cog * 8 + 2 * g;
        if (co0 < COUT) {
            float* b = out + ((size_t)(n * COUT + co0) * HP + gy + 1) * WP + gx0 + x0 + 1;
#pragma unroll
            for (int p = 0; p < 8; ++p) b[p] = fmaxf(lo_f(acc[g][p]), 0.f);
        }
        if (co0 + 1 < COUT) {
            float* b = out + ((size_t)(n * COUT + co0 + 1) * HP + gy + 1) * WP + gx0 + x0 + 1;
#pragma unroll
            for (int p = 0; p < 8; ++p) b[p] = fmaxf(hi_f(acc[g][p]), 0.f);
        }
    }
}

// ---------------------------------------------------------------------------
// Weight pre-pack: (co,co+1) u64 pairs, chunk-major (matches stage() layout)
// ---------------------------------------------------------------------------
__global__ void prepack(const float* __restrict__ w, unsigned long long* __restrict__ dst,
                        int COUT, int CIN, int CO_TILE, int CO_PAD, int CC) {
    int NCH = CIN / CC, TIL = (COUT + CO_TILE - 1) / CO_TILE;
    int total = TIL * NCH * (CO_PAD / 2) * CC * 9;
    for (int i = blockIdx.x * blockDim.x + threadIdx.x; i < total;
         i += gridDim.x * blockDim.x) {
        int k = i % 9;  int t = i / 9;
        int cc = t % CC;               t /= CC;
        int cp = t % (CO_PAD / 2);     t /= (CO_PAD / 2);
        int ch = t % NCH;
        int tile = t / NCH;
        int co0 = tile * CO_TILE + 2 * cp;
        int ci  = ch * CC + cc;
        float lo = (co0     < COUT) ? w[(co0       * CIN + ci) * 9 + k] : 0.f;
        float hi = (co0 + 1 < COUT) ? w[((co0 + 1) * CIN + ci) * 9 + k] : 0.f;
        unsigned long long r = (unsigned long long)__float_as_uint(lo)
                             | ((unsigned long long)__float_as_uint(hi) << 32);
        dst[i] = r;
    }
}

// ---------------------------------------------------------------------------
// Pad network input x (N,1,256,256) -> (N, 258, 260) with zero borders
// ---------------------------------------------------------------------------
__global__ void pad_x(const float* __restrict__ x, float* __restrict__ xp, int N) {
    int total = N * 258 * 260;
    for (int i = blockIdx.x * blockDim.x + threadIdx.x; i < total;
         i += gridDim.x * blockDim.x) {
        int c = i % 260, r = (i / 260) % 258, n = i / (260 * 258);
        float v = 0.f;
        if (r >= 1 && r <= 256 && c >= 1 && c <= 256)
            v = x[(n * 256 + r - 1) * 256 + c - 1];
        xp[i] = v;
    }
}

// ---------------------------------------------------------------------------
// Zero the borders of a padded tensor (rows 0 & HP-1; cols 0, W+1..W+3)
// ---------------------------------------------------------------------------
__global__ void zero_border(float* __restrict__ buf, int planes, int H, int W) {
    int HP = H + 2, WP = W + 4;
    int per = 2 * WP + (HP - 2) * 4;
    int total = planes * per;
    for (int i = blockIdx.x * blockDim.x + threadIdx.x; i < total;
         i += gridDim.x * blockDim.x) {
        int p = i / per, j = i % per;
        int r, c;
        if (j < WP)           { r = 0;      c = j; }
        else if (j < 2 * WP)  { r = HP - 1; c = j - WP; }
        else {
            int t = j - 2 * WP;
            r = 1 + t / 4;
            int q = t % 4;
            c = (q == 0) ? 0 : (W + q);
        }
        buf[(size_t)p * HP * WP + r * WP + c] = 0.f;
    }
}

// ---------------------------------------------------------------------------
// PixelShuffle(4) + ReLU: A_pd (16ch @258x260) -> Hh_pd (1ch @1026x1028)
// ---------------------------------------------------------------------------
__global__ void pixel_shuffle_relu(const float* __restrict__ in,
                                   float* __restrict__ out, int total) {
    for (int i = blockIdx.x * blockDim.x + threadIdx.x; i < total;
         i += gridDim.x * blockDim.x) {
        int x = i & 1023, y = (i >> 10) & 1023, n = i >> 20;
        int c = (y & 3) * 4 + (x & 3);
        float v = in[((n * 16 + c) * 258 + (y >> 2) + 1) * 260 + (x >> 2) + 1];
        out[(n * 1026 + y + 1) * 1028 + x + 1] = fmaxf(v, 0.f);
    }
}

// ---------------------------------------------------------------------------
// Per-pixel 5x5 dynamic kernel conv + residual add (padded h and z inputs).
// ---------------------------------------------------------------------------
__global__ void pixel_conv_add(const float* __restrict__ h,
                               const float* __restrict__ z,
                               float* __restrict__ out) {
    __shared__ float sh[20][21];
    const int n   = blockIdx.z;
    const int gx0 = blockIdx.x * 16;
    const int gy0 = blockIdx.y * 16;
    const int tx = threadIdx.x, ty = threadIdx.y;
    const int tid = ty * 16 + tx;

    for (int i = tid; i < 400; i += 256) {
        int r = i / 20, c = i % 20;
        int gy = gy0 + r - 2, gx = gx0 + c - 2;
        float v = 0.f;
        if ((unsigned)gy < 1024u && (unsigned)gx < 1024u)
            v = h[(n * 1026 + gy + 1) * 1028 + gx + 1];
        sh[r][c] = v;
    }
    __syncthreads();

    const int y = gy0 + ty, x = gx0 + tx;
    float acc = sh[ty + 2][tx + 2];
    const float* zp = z + ((size_t)(n * 25) * 1026 + (y + 1)) * 1028 + x + 1;
#pragma unroll
    for (int j = 0; j < 25; ++j)
        acc = fmaf(sh[ty + (j % 5)][tx + (j / 5)], zp[(size_t)j * 1026 * 1028], acc);
    out[(n * 1024 + y) * 1024 + x] = acc;
}

// ---------------------------------------------------------------------------
// Launch plumbing
// ---------------------------------------------------------------------------
template <int CIN, int COUT>
static void launch_conv(const float* in, const unsigned long long* wp, float* out,
                        int N, int H, int W) {
    constexpr int CO_TILE  = (COUT > 32) ? 32 : COUT;
    constexpr int CO_TILES = (COUT + CO_TILE - 1) / CO_TILE;
    dim3 grid(W / 32, H / 8, N * CO_TILES);
    conv3x3_cp<CIN, COUT><<<grid, CONV_NT(COUT)>>>(in, wp, out, H, W);
}

extern "C" void kernel_launch(void* const* d_in, const int* in_sizes, int n_in,
                              void* d_out, int out_size) {
    const float* x    = (const float*)d_in[0];
    const float* w_e1 = (const float*)d_in[1];
    const float* w_e2 = (const float*)d_in[2];
    const float* w_e3 = (const float*)d_in[3];
    const float* w_d1 = (const float*)d_in[4];
    const float* w_d2 = (const float*)d_in[5];
    const float* w_k1 = (const float*)d_in[6];
    const float* w_k2 = (const float*)d_in[7];
    const float* w_k3 = (const float*)d_in[8];
    const float* w_k4 = (const float*)d_in[9];
    float* out = (float*)d_out;

    const int N = in_sizes[0] / (256 * 256);   // 2

    float *A, *B, *Hh, *Xp;
    unsigned long long* Wp;
    cudaGetSymbolAddress((void**)&A,  g_bufA);
    cudaGetSymbolAddress((void**)&B,  g_bufB);
    cudaGetSymbolAddress((void**)&Hh, g_h);
    cudaGetSymbolAddress((void**)&Xp, g_xpad);
    cudaGetSymbolAddress((void**)&Wp, g_wpack);

    // weight pre-pack (offsets precomputed for the 9 layers)
    prepack<<<4,  256>>>(w_e1, Wp + 0,     16, 1,  16, 16, 1);
    prepack<<<9,  256>>>(w_e2, Wp + 72,    32, 16, 32, 32, 4);
    prepack<<<36, 256>>>(w_e3, Wp + 2376,  64, 32, 32, 32, 4);
    prepack<<<36, 256>>>(w_d1, Wp + 11592, 32, 64, 32, 32, 4);
    prepack<<<9,  256>>>(w_d2, Wp + 20808, 16, 32, 16, 16, 4);
    prepack<<<4,  256>>>(w_k1, Wp + 23112, 32, 1,  32, 32, 1);
    prepack<<<36, 256>>>(w_k2, Wp + 23256, 64, 32, 32, 32, 4);
    prepack<<<36, 256>>>(w_k3, Wp + 32472, 32, 64, 32, 32, 4);
    prepack<<<18, 256>>>(w_k4, Wp + 41688, 25, 32, 25, 32, 4);

    // input padding + small-geometry & shuffled-image border zeroing
    pad_x<<<132, 256>>>(x, Xp, N);
    zero_border<<<200, 256>>>(A,  N * 64, 256, 256);
    zero_border<<<200, 256>>>(B,  N * 64, 256, 256);
    zero_border<<<40,  256>>>(Hh, N,      1024, 1024);

    // encoder / decoder @ 256x256 (padded)
    launch_conv<1, 16>(Xp, Wp + 0,     A, N, 256, 256);
    launch_conv<16, 32>(A, Wp + 72,    B, N, 256, 256);
    launch_conv<32, 64>(B, Wp + 2376,  A, N, 256, 256);
    launch_conv<64, 32>(A, Wp + 11592, B, N, 256, 256);
    launch_conv<32, 16>(B, Wp + 20808, A, N, 256, 256);

    // pixel shuffle + relu -> padded 1026x1028 image
    pixel_shuffle_relu<<<2048, 256>>>(A, Hh, N * 1024 * 1024);

    // re-zero borders for the big geometry (small-phase writes dirtied them)
    zero_border<<<800, 256>>>(A, N * 64, 1024, 1024);
    zero_border<<<800, 256>>>(B, N * 64, 1024, 1024);

    // kernel-prediction branch @ 1024x1024 (padded)
    launch_conv<1, 32>(Hh, Wp + 23112, A, N, 1024, 1024);
    launch_conv<32, 64>(A, Wp + 23256, B, N, 1024, 1024);
    launch_conv<64, 32>(B, Wp + 32472, A, N, 1024, 1024);
    launch_conv<32, 25>(A, Wp + 41688, B, N, 1024, 1024);

    // per-pixel kernel application + residual
    dim3 grid(1024 / 16, 1024 / 16, N);
    pixel_conv_add<<<grid, dim3(16, 16)>>>(Hh, B, out);
}

// round 13
// speedup vs baseline: 1.2302x; 1.2302x over previous
#include <cuda_runtime.h>
#include <cuda_bf16.h>
#include <cstdint>

// ---------------------------------------------------------------------------
// Scratch buffers (allocation-free: __device__ globals)
// ---------------------------------------------------------------------------
__device__ float g_bufA[2 * 64 * 1024 * 1024];
__device__ float g_bufB[2 * 64 * 1024 * 1024];
__device__ float g_h[2 * 1024 * 1024];  // pixel-shuffled image (N,1,1024,1024)

// ---------------------------------------------------------------------------
// Packed f32x2 helpers (sm_103a FFMA2 — 2 fp32 MACs per issue slot)
// ---------------------------------------------------------------------------
__device__ __forceinline__ void ffma2(uint64_t& d, uint64_t a, uint64_t b) {
    asm("fma.rn.f32x2 %0, %1, %2, %0;" : "+l"(d) : "l"(a), "l"(b));
}
__device__ __forceinline__ uint64_t dup2f(float v) {
    uint64_t r; asm("mov.b64 %0, {%1, %1};" : "=l"(r) : "f"(v)); return r;
}
__device__ __forceinline__ uint64_t pack2(float lo, float hi) {
    return (uint64_t)__float_as_uint(lo) | ((uint64_t)__float_as_uint(hi) << 32);
}
__device__ __forceinline__ float lo_f(uint64_t v) { return __uint_as_float((uint32_t)v); }
__device__ __forceinline__ float hi_f(uint64_t v) { return __uint_as_float((uint32_t)(v >> 32)); }

// Threads per block: one co-tile covers ALL of COUT (16->64t, 25/32->128t, 64->256t)
#define CONV_NT2(COUT) (((((COUT) >= 64) ? 64 : (((COUT) + 7) & ~7)) / 8) * 32)

// ---------------------------------------------------------------------------
// conv3x3 + ReLU, FFMA2, software-pipelined staging (double-buffered smem).
//   Pixel tile 32x8. Thread: 8 x-pixels x 8 output channels (4 f32x2 pairs).
//   Input smem: PLAIN floats, row stride 36 (16B-aligned, conflict-free
//   LDS.128 phases). Compute: 3x LDS.128 -> 12 floats -> dup via mov.b64
//   (ALU pipe, hidden under FFMA2 rt=2 gaps). Crossbar load: 48B/step vs 80B
//   for the old duplicated-smem scheme (which exceeded 128B/cyc/SM at 16 warps).
// ---------------------------------------------------------------------------
template <int CIN, int COUT>
__global__ void __launch_bounds__(CONV_NT2(COUT), 512 / CONV_NT2(COUT))
conv3x3_pipe(const float* __restrict__ in,
             const float* __restrict__ w,
             float* __restrict__ out,
             int H, int W) {
    constexpr int CO_PAD    = (COUT >= 64) ? 64 : ((COUT + 7) & ~7);  // 16/32/32/64
    constexpr int CO_GROUPS = CO_PAD / 8;
    constexpr int NT        = CO_GROUPS * 32;
    static_assert(NT == CONV_NT2(COUT), "launch bounds mismatch");
    constexpr int CC     = (CIN >= 4) ? 4 : CIN;
    constexpr int NCHUNK = CIN / CC;
    constexpr int SF     = 36;                       // floats per smem row (16B-aligned)
    constexpr int IN_ELEMS = CC * 10 * SF;
    constexpr int W_ELEMS  = (CO_PAD / 2) * CC * 9;
    constexpr int PF_IN = (IN_ELEMS + NT - 1) / NT;
    constexpr int PF_W  = (W_ELEMS + NT - 1) / NT;
    constexpr bool PIPE = (NT >= 128) && (NCHUNK > 1);
    constexpr int NBUF  = PIPE ? 2 : 1;

    __shared__ __align__(16) float s_in[NBUF][CC][10][SF];
    __shared__ __align__(16) uint64_t s_w2[NBUF][CO_PAD / 2][CC][9];

    const int tid = threadIdx.x;
    const int n   = blockIdx.z;
    const int gx0 = blockIdx.x * 32;
    const int gy0 = blockIdx.y * 8;

    const int cog = tid >> 5;          // co-group 0..CO_GROUPS-1
    const int pix = tid & 31;
    const int row = pix >> 2;          // 0..7
    const int x0  = (pix & 3) * 8;     // 0,8,16,24

    uint64_t acc[4][8];
#pragma unroll
    for (int g = 0; g < 4; ++g)
#pragma unroll
        for (int p = 0; p < 8; ++p) acc[g][p] = 0ull;

    float vi[PF_IN];
    float vw[2 * PF_W];

    // ---- staging helpers ----
    auto ldg_in = [&](int c0) {
#pragma unroll
        for (int t = 0; t < PF_IN; ++t) {
            int i = tid + t * NT;
            float v = 0.f;
            if (i < IN_ELEMS) {
                int c = i / (10 * SF);
                int rem = i % (10 * SF);
                int r = rem / SF, sx = rem % SF;
                int gy = gy0 + r - 1, gx = gx0 + sx - 1;
                if ((unsigned)gy < (unsigned)H && (unsigned)gx < (unsigned)W)
                    v = in[((n * CIN + c0 + c) * H + gy) * W + gx];
            }
            vi[t] = v;
        }
    };
    auto ldg_w = [&](int c0) {
#pragma unroll
        for (int t = 0; t < PF_W; ++t) {
            int i = tid + t * NT;
            float a = 0.f, b = 0.f;
            if (i < W_ELEMS) {
                int cp = i / (CC * 9);
                int rem = i % (CC * 9);
                int c = rem / 9, k = rem % 9;
                int co0 = cp * 2;
                if (co0 < COUT)     a = w[((co0)     * CIN + c0 + c) * 9 + k];
                if (co0 + 1 < COUT) b = w[((co0 + 1) * CIN + c0 + c) * 9 + k];
            }
            vw[2 * t] = a; vw[2 * t + 1] = b;
        }
    };
    auto sts_chunk = [&](int buf) {
#pragma unroll
        for (int t = 0; t < PF_IN; ++t) {
            int i = tid + t * NT;
            if (i < IN_ELEMS) (&s_in[buf][0][0][0])[i] = vi[t];
        }
#pragma unroll
        for (int t = 0; t < PF_W; ++t) {
            int i = tid + t * NT;
            if (i < W_ELEMS) (&s_w2[buf][0][0][0])[i] = pack2(vw[2 * t], vw[2 * t + 1]);
        }
    };
    auto compute = [&](int buf) {
#pragma unroll
        for (int c = 0; c < CC; ++c) {
#pragma unroll
            for (int ky = 0; ky < 3; ++ky) {
                const float* rp = &s_in[buf][c][row + ky][x0];
                float4 A4 = *(const float4*)rp;
                float4 B4 = *(const float4*)(rp + 4);
                float4 C4 = *(const float4*)(rp + 8);
                uint64_t D[10];
                D[0] = dup2f(A4.x); D[1] = dup2f(A4.y);
                D[2] = dup2f(A4.z); D[3] = dup2f(A4.w);
                D[4] = dup2f(B4.x); D[5] = dup2f(B4.y);
                D[6] = dup2f(B4.z); D[7] = dup2f(B4.w);
                D[8] = dup2f(C4.x); D[9] = dup2f(C4.y);
#pragma unroll
                for (int g = 0; g < 4; ++g) {
                    const uint64_t w0 = s_w2[buf][cog * 4 + g][c][ky * 3 + 0];
                    const uint64_t w1 = s_w2[buf][cog * 4 + g][c][ky * 3 + 1];
                    const uint64_t w2 = s_w2[buf][cog * 4 + g][c][ky * 3 + 2];
#pragma unroll
                    for (int p = 0; p < 8; ++p) {
                        ffma2(acc[g][p], D[p],     w0);
                        ffma2(acc[g][p], D[p + 1], w1);
                        ffma2(acc[g][p], D[p + 2], w2);
                    }
                }
            }
        }
    };

    if (PIPE) {
        // prologue: stage chunk 0 into buffer 0
        ldg_in(0); ldg_w(0); sts_chunk(0);
        __syncthreads();
        for (int ch = 0; ch < NCHUNK; ++ch) {
            const int cur = ch & 1;
            if (ch + 1 < NCHUNK) ldg_in((ch + 1) * CC);   // in flight during compute
            compute(cur);
            if (ch + 1 < NCHUNK) {
                ldg_w((ch + 1) * CC);                      // small, L2-hot
                sts_chunk(cur ^ 1);
            }
            __syncthreads();                               // one sync per chunk
        }
    } else {
        for (int ch = 0; ch < NCHUNK; ++ch) {
            ldg_in(ch * CC); ldg_w(ch * CC);
            if (ch) __syncthreads();                       // all done reading buf
            sts_chunk(0);
            __syncthreads();
            compute(0);
        }
    }

    // ---- fused ReLU + vectorized store ----
    const int gy = gy0 + row;
#pragma unroll
    for (int g = 0; g < 4; ++g) {
        const int co0 = cog * 8 + 2 * g;
        if (co0 < COUT) {
            float4 a, b;
            a.x = fmaxf(lo_f(acc[g][0]), 0.f); a.y = fmaxf(lo_f(acc[g][1]), 0.f);
            a.z = fmaxf(lo_f(acc[g][2]), 0.f); a.w = fmaxf(lo_f(acc[g][3]), 0.f);
            b.x = fmaxf(lo_f(acc[g][4]), 0.f); b.y = fmaxf(lo_f(acc[g][5]), 0.f);
            b.z = fmaxf(lo_f(acc[g][6]), 0.f); b.w = fmaxf(lo_f(acc[g][7]), 0.f);
            float4* op = (float4*)&out[((n * COUT + co0) * H + gy) * W + gx0 + x0];
            op[0] = a; op[1] = b;
        }
        if (co0 + 1 < COUT) {
            float4 a, b;
            a.x = fmaxf(hi_f(acc[g][0]), 0.f); a.y = fmaxf(hi_f(acc[g][1]), 0.f);
            a.z = fmaxf(hi_f(acc[g][2]), 0.f); a.w = fmaxf(hi_f(acc[g][3]), 0.f);
            b.x = fmaxf(hi_f(acc[g][4]), 0.f); b.y = fmaxf(hi_f(acc[g][5]), 0.f);
            b.z = fmaxf(hi_f(acc[g][6]), 0.f); b.w = fmaxf(hi_f(acc[g][7]), 0.f);
            float4* op = (float4*)&out[((n * COUT + co0 + 1) * H + gy) * W + gx0 + x0];
            op[0] = a; op[1] = b;
        }
    }
}

// ---------------------------------------------------------------------------
// PixelShuffle(4) + ReLU: (N,16,256,256) -> (N,1,1024,1024)
// ---------------------------------------------------------------------------
__global__ void pixel_shuffle_relu(const float* __restrict__ in,
                                   float* __restrict__ out, int total) {
    int idx = blockIdx.x * blockDim.x + threadIdx.x;
    if (idx >= total) return;
    int x = idx & 1023;
    int y = (idx >> 10) & 1023;
    int n = idx >> 20;
    int c = (y & 3) * 4 + (x & 3);
    float v = in[((n * 16 + c) * 256 + (y >> 2)) * 256 + (x >> 2)];
    out[idx] = fmaxf(v, 0.f);
}

// ---------------------------------------------------------------------------
// Per-pixel 5x5 dynamic kernel conv + residual add.
//   out[n,y,x] = h[n,y,x] + sum_j hpad(y + j%5 - 2, x + j/5 - 2) * z[n,j,y,x]
// ---------------------------------------------------------------------------
__global__ void pixel_conv_add(const float* __restrict__ h,
                               const float* __restrict__ z,
                               float* __restrict__ out) {
    const int HH = 1024, WW = 1024;
    __shared__ float sh[20][21];

    const int n   = blockIdx.z;
    const int gx0 = blockIdx.x * 16;
    const int gy0 = blockIdx.y * 16;
    const int tx = threadIdx.x, ty = threadIdx.y;
    const int tid = ty * 16 + tx;

    for (int i = tid; i < 400; i += 256) {
        int r = i / 20, c = i % 20;
        int gy = gy0 + r - 2, gx = gx0 + c - 2;
        float v = 0.f;
        if (gy >= 0 && gy < HH && gx >= 0 && gx < WW)
            v = h[(n * HH + gy) * WW + gx];
        sh[r][c] = v;
    }
    __syncthreads();

    const int y = gy0 + ty, x = gx0 + tx;
    float acc = sh[ty + 2][tx + 2];
    const float* zp = z + (n * 25 * HH + y) * WW + x;
#pragma unroll
    for (int j = 0; j < 25; ++j)
        acc = fmaf(sh[ty + (j % 5)][tx + (j / 5)], zp[j * HH * WW], acc);
    out[(n * HH + y) * WW + x] = acc;
}

// ---------------------------------------------------------------------------
// Launch plumbing — one co-tile covers all COUT; grid z = batch only.
// ---------------------------------------------------------------------------
template <int CIN, int COUT>
static void launch_conv(const float* in, const float* w, float* out,
                        int N, int H, int W) {
    dim3 grid(W / 32, H / 8, N);
    conv3x3_pipe<CIN, COUT><<<grid, CONV_NT2(COUT)>>>(in, w, out, H, W);
}

extern "C" void kernel_launch(void* const* d_in, const int* in_sizes, int n_in,
                              void* d_out, int out_size) {
    const float* x    = (const float*)d_in[0];
    const float* w_e1 = (const float*)d_in[1];
    const float* w_e2 = (const float*)d_in[2];
    const float* w_e3 = (const float*)d_in[3];
    const float* w_d1 = (const float*)d_in[4];
    const float* w_d2 = (const float*)d_in[5];
    const float* w_k1 = (const float*)d_in[6];
    const float* w_k2 = (const float*)d_in[7];
    const float* w_k3 = (const float*)d_in[8];
    const float* w_k4 = (const float*)d_in[9];
    float* out = (float*)d_out;

    const int N = in_sizes[0] / (256 * 256);   // N=2

    float *A, *B, *Hh;
    cudaGetSymbolAddress((void**)&A,  g_bufA);
    cudaGetSymbolAddress((void**)&B,  g_bufB);
    cudaGetSymbolAddress((void**)&Hh, g_h);

    // encoder / decoder @ 256x256
    launch_conv<1, 16>(x, w_e1, A, N, 256, 256);
    launch_conv<16, 32>(A, w_e2, B, N, 256, 256);
    launch_conv<32, 64>(B, w_e3, A, N, 256, 256);
    launch_conv<64, 32>(A, w_d1, B, N, 256, 256);
    launch_conv<32, 16>(B, w_d2, A, N, 256, 256);

    // pixel shuffle + relu -> (N,1,1024,1024)
    {
        int total = N * 1024 * 1024;
        pixel_shuffle_relu<<<(total + 255) / 256, 256>>>(A, Hh, total);
    }

    // kernel-prediction branch @ 1024x1024
    launch_conv<1, 32>(Hh, w_k1, A, N, 1024, 1024);
    launch_conv<32, 64>(A, w_k2, B, N, 1024, 1024);
    launch_conv<64, 32>(B, w_k3, A, N, 1024, 1024);
    launch_conv<32, 25>(A, w_k4, B, N, 1024, 1024);

    // per-pixel kernel application + residual
    {
        dim3 grid(1024 / 16, 1024 / 16, N);
        dim3 blk(16, 16);
        pixel_conv_add<<<grid, blk>>>(Hh, B, out);
    }
}